// round 1
// baseline (speedup 1.0000x reference)
#include <cuda_runtime.h>

#define BB 512
#define KK 800
#define DD 512

__global__ __launch_bounds__(256) void sparse_linear_kernel(
    const float* __restrict__ embed,
    const int*   __restrict__ shortlist,
    const float* __restrict__ sp_weight,
    const float* __restrict__ sp_bias,
    float*       __restrict__ out)
{
    __shared__ float4 s_embed[DD / 4];

    const int b = blockIdx.x;

    // Stage embed[b,:] (2 KB) in shared: read once, reused K=800 times.
    const float4* erow = reinterpret_cast<const float4*>(embed + (size_t)b * DD);
    for (int i = threadIdx.x; i < DD / 4; i += blockDim.x)
        s_embed[i] = erow[i];
    __syncthreads();

    const int warp  = threadIdx.x >> 5;
    const int lane  = threadIdx.x & 31;
    const int nwarp = blockDim.x >> 5;

    for (int k = warp; k < KK; k += nwarp) {
        const int idx = shortlist[b * KK + k];
        const float4* wrow =
            reinterpret_cast<const float4*>(sp_weight + (long long)idx * DD);

        float sum = 0.0f;
        #pragma unroll
        for (int i = 0; i < DD / 128; ++i) {   // 4 iterations, 4 independent LDG.128
            float4 w = wrow[i * 32 + lane];
            float4 e = s_embed[i * 32 + lane];
            sum = fmaf(w.x, e.x, sum);
            sum = fmaf(w.y, e.y, sum);
            sum = fmaf(w.z, e.z, sum);
            sum = fmaf(w.w, e.w, sum);
        }

        // warp tree reduction
        #pragma unroll
        for (int off = 16; off; off >>= 1)
            sum += __shfl_xor_sync(0xffffffffu, sum, off);

        if (lane == 0)
            out[b * KK + k] = sum + __ldg(&sp_bias[idx]);
    }
}

extern "C" void kernel_launch(void* const* d_in, const int* in_sizes, int n_in,
                              void* d_out, int out_size) {
    const float* embed     = (const float*)d_in[0];
    const int*   shortlist = (const int*)  d_in[1];
    const float* sp_weight = (const float*)d_in[2];
    const float* sp_bias   = (const float*)d_in[3];
    float*       out       = (float*)d_out;

    sparse_linear_kernel<<<BB, 256>>>(embed, shortlist, sp_weight, sp_bias, out);
}